// round 13
// baseline (speedup 1.0000x reference)
#include <cuda_runtime.h>
#include <cuda_fp16.h>
#include <stdint.h>

#define BQ 1024
#define DD 512
#define NP 65536
#define NSTEPS 10
#define KSPLIT 9
#define NT1 37                              // GEMM1 grid.x (persistent): 37*8=296 CTAs

#define BM 128
#define BN 128
#define BK 64
#define PANEL_H 8192                        // halves per 128x64 fp16 panel
#define PANEL_B 16384                       // bytes per panel
#define STAGE_B (2 * PANEL_B)               // A + B per stage
#define NSTG 3
#define RING_OFF 5120                       // bytes: 1024 hdr (mbars) + 4096 lsum scratch
#define SMEM_BYTES (RING_OFF + NSTG * STAGE_B)   // 103424 -> 2 CTAs/SM

// mbar layout (bytes from sbase): full[b] at 8*b, empty[b] at 24 + 8*b

// ---------------- tiled global scratch (device globals; no allocation) ----------------
// fp16 panel [128 r][64 cl], SW128: half index = r*64 + (((cl>>1) ^ ((r&7)<<2))<<1) + (cl&1)
// 16B-chunk view: chunk ch of row r lives at byte r*128 + ((ch ^ (r&7))<<4)
__device__ __half g_S_h[(size_t)8 * 1024 * PANEL_H];     // weights tiled [mblk][kstg] 134MB
__device__ __half g_patt_h[(size_t)512 * 8 * PANEL_H];   // P tiled [nblk][dstg]        67MB
__device__ __half g_pattT_h[(size_t)4 * 1024 * PANEL_H]; // P^T tiled [jblk][nstg]      67MB
__device__ __half g_state_ht[(size_t)8 * 8 * PANEL_H];   // fp16(state/b) tiled          1MB
__device__ float g_state[BQ * DD];                       // fp32 state (output)
__device__ float g_lpart[(size_t)BQ * (NP / BN)];        // per-tile weight sums
__device__ float g_ssq[BQ];
__device__ float g_ea[BQ];                               // b = ||state||
__device__ float g_eb[BQ];                               // k*ln2 - b  (k = floor(b/ln2))
__device__ float g_energy[(NSTEPS + 1) * BQ];
__device__ float g_part[(size_t)KSPLIT * BQ * DD];       // GEMM2 split-K partials 18MB

// ---------------- helpers ----------------
__device__ __forceinline__ uint32_t swzh(uint32_t r, uint32_t cl) {
    return r * 64u + ((((cl >> 1) ^ ((r & 7u) << 2)) << 1)) + (cl & 1u);
}
__device__ __forceinline__ void mbar_init(uint32_t addr, uint32_t cnt) {
    asm volatile("mbarrier.init.shared.b64 [%0], %1;" ::"r"(addr), "r"(cnt) : "memory");
}
__device__ __forceinline__ void mbar_expect_tx(uint32_t addr, uint32_t bytes) {
    asm volatile("mbarrier.arrive.expect_tx.shared.b64 _, [%0], %1;"
                 ::"r"(addr), "r"(bytes) : "memory");
}
__device__ __forceinline__ void mbar_arrive(uint32_t addr) {
    asm volatile("mbarrier.arrive.shared.b64 _, [%0];" ::"r"(addr) : "memory");
}
__device__ __forceinline__ void mbar_wait(uint32_t addr, uint32_t parity) {
    asm volatile(
        "{\n\t.reg .pred P1;\n\t"
        "WAIT_%=:\n\t"
        "mbarrier.try_wait.parity.acquire.cta.shared::cta.b64 P1, [%0], %1, 0x989680;\n\t"
        "@!P1 bra WAIT_%=;\n\t"
        "}"
        ::"r"(addr), "r"(parity) : "memory");
}
__device__ __forceinline__ void bulk_g2s(uint32_t daddr, const void* src, uint32_t bytes,
                                         uint32_t mbar) {
    asm volatile(
        "cp.async.bulk.shared::cluster.global.mbarrier::complete_tx::bytes "
        "[%0], [%1], %2, [%3];"
        ::"r"(daddr), "l"(src), "r"(bytes), "r"(mbar) : "memory");
}

#define LDSM_X4(d0, d1, d2, d3, a)                                                     \
    asm volatile("ldmatrix.sync.aligned.m8n8.x4.shared.b16 {%0,%1,%2,%3}, [%4];"       \
                 : "=r"(d0), "=r"(d1), "=r"(d2), "=r"(d3)                              \
                 : "r"(a))

// per-thread fragment constants (computed once per kernel):
//   lrow = lane&7; lch = (lane>>4)&1; lchB = (lane>>3)&1;
//   arow128[mi] = (wm*64 + mi*16 + ((lane>>3)&1)*8 + lrow) * 128
//   brow128[p]  = (wn*32 + p*16  + ((lane>>4)&1)*8 + lrow) * 128
#define FRAG_MMA_BODY(Asb, Bsb)                                                        \
    _Pragma("unroll") for (int kk = 0; kk < 4; kk++) {                                 \
        uint32_t offA = (uint32_t)(((2 * kk + lch) ^ lrow) << 4);                      \
        uint32_t offB = (uint32_t)(((2 * kk + lchB) ^ lrow) << 4);                     \
        uint32_t af[4][4], bf[4][2];                                                   \
        _Pragma("unroll") for (int mi = 0; mi < 4; mi++)                               \
            LDSM_X4(af[mi][0], af[mi][1], af[mi][2], af[mi][3],                        \
                    (Asb) + arow128[mi] + offA);                                       \
        _Pragma("unroll") for (int p = 0; p < 2; p++)                                  \
            LDSM_X4(bf[2 * p][0], bf[2 * p][1], bf[2 * p + 1][0], bf[2 * p + 1][1],    \
                    (Bsb) + brow128[p] + offB);                                        \
        _Pragma("unroll") for (int mi = 0; mi < 4; mi++)                               \
            _Pragma("unroll") for (int ni = 0; ni < 4; ni++) {                         \
                asm volatile(                                                          \
                    "mma.sync.aligned.m16n8k16.row.col.f32.f16.f16.f32 "               \
                    "{%0,%1,%2,%3}, {%4,%5,%6,%7}, {%8,%9}, {%0,%1,%2,%3};\n"          \
                    : "+f"(acc[mi][ni][0]), "+f"(acc[mi][ni][1]),                      \
                      "+f"(acc[mi][ni][2]), "+f"(acc[mi][ni][3])                       \
                    : "r"(af[mi][0]), "r"(af[mi][1]), "r"(af[mi][2]), "r"(af[mi][3]),  \
                      "r"(bf[ni][0]), "r"(bf[ni][1]));                                 \
            }                                                                          \
    }

#define FRAG_CONSTS()                                                                 \
    const int lrow = lane & 7;                                                        \
    const int lch = (lane >> 4) & 1;                                                  \
    const int lchB = (lane >> 3) & 1;                                                 \
    uint32_t arow128[4], brow128[2];                                                  \
    _Pragma("unroll") for (int mi = 0; mi < 4; mi++)                                  \
        arow128[mi] = (wm * 64 + mi * 16 + ((lane >> 3) & 1) * 8 + lrow) * 128;       \
    _Pragma("unroll") for (int p = 0; p < 2; p++)                                     \
        brow128[p] = (wn * 32 + p * 16 + ((lane >> 4) & 1) * 8 + lrow) * 128;

// consume stage u from buffer b with producer refill of u+NSTG
#define PIPE_STAGE(u, total, STAGE_FN)                                                 \
    {                                                                                  \
        int b_ = (u) % NSTG;                                                           \
        uint32_t fullb_ = sbase + 8 * b_;                                              \
        uint32_t emptyb_ = sbase + 24 + 8 * b_;                                        \
        uint32_t par_ = ((u) / NSTG) & 1;                                              \
        mbar_wait(fullb_, par_);                                                       \
        uint32_t Asb_ = sbase + RING_OFF + b_ * STAGE_B;                               \
        uint32_t Bsb_ = Asb_ + PANEL_B;                                                \
        FRAG_MMA_BODY(Asb_, Bsb_)                                                      \
        if (lane == 0) mbar_arrive(emptyb_);                                           \
        if (tid == 0 && (u) + NSTG < (total)) {                                        \
            mbar_wait(emptyb_, par_);                                                  \
            STAGE_FN((u) + NSTG);                                                      \
        }                                                                              \
    }

// =================================================================
// GEMM1 (persistent): grid (37, 8), 256 threads, 2 CTAs/SM.
// producer/consumer mbarrier pipeline; epilogue w'=exp(b*acc+cb) + row sums
// =================================================================
__global__ __launch_bounds__(256, 2) void gemm1_ms(int store_w) {
    extern __shared__ float sm[];
    const uint32_t sbase = (uint32_t)__cvta_generic_to_shared(sm);

    const int tid = threadIdx.x;
    const int wid = tid >> 5, lane = tid & 31;
    const int wm = wid >> 2, wn = wid & 3;
    const int g = lane >> 2, c = lane & 3;
    const int bx = blockIdx.x, by = blockIdx.y;
    const int t0 = (bx * 512) / NT1, t1 = ((bx + 1) * 512) / NT1;
    const int total = (t1 - t0) * 8;
    FRAG_CONSTS()

    if (tid == 0) {
#pragma unroll
        for (int b = 0; b < NSTG; b++) {
            mbar_init(sbase + 8 * b, 1);       // full
            mbar_init(sbase + 24 + 8 * b, 8);  // empty (8 warps)
        }
        asm volatile("fence.proxy.async.shared::cta;" ::: "memory");
    }
    __syncthreads();

    auto stage = [&](int u) {
        int b = u % NSTG;
        uint32_t mbar = sbase + 8 * b;
        uint32_t da = sbase + RING_OFF + b * STAGE_B;
        int tile = t0 + (u >> 3), k = u & 7;
        mbar_expect_tx(mbar, STAGE_B);
        bulk_g2s(da, g_state_ht + ((size_t)by * 8 + k) * PANEL_H, PANEL_B, mbar);
        bulk_g2s(da + PANEL_B, g_patt_h + ((size_t)tile * 8 + k) * PANEL_H, PANEL_B, mbar);
    };
    if (tid == 0) { stage(0); stage(1); stage(2); }

    float bbv[4][2], cbv[4][2];
#pragma unroll
    for (int mi = 0; mi < 4; mi++) {
        int r0 = wm * 64 + mi * 16 + g;
        bbv[mi][0] = g_ea[by * BM + r0];
        cbv[mi][0] = g_eb[by * BM + r0];
        bbv[mi][1] = g_ea[by * BM + r0 + 8];
        cbv[mi][1] = g_eb[by * BM + r0 + 8];
    }

    float* lsum = sm + 256;  // bytes [1024, 5120): dedicated scratch, [128][4]

    int u = 0;
    for (int tile = t0; tile < t1; tile++) {
        float acc[4][4][4];
#pragma unroll
        for (int i = 0; i < 4; i++)
#pragma unroll
            for (int j = 0; j < 4; j++)
#pragma unroll
                for (int r = 0; r < 4; r++) acc[i][j][r] = 0.f;

        for (int k = 0; k < 8; k++, u++) {
            PIPE_STAGE(u, total, stage)
        }

        // ---- epilogue: w' = exp(b*acc + cb), fp16 tiled store + row sums ----
        __half* Sp = g_S_h + ((size_t)by * 1024 + tile * 2 + (wn >> 1)) * PANEL_H;
#pragma unroll
        for (int mi = 0; mi < 4; mi++) {
            int r0 = wm * 64 + mi * 16 + g;
            float s0 = 0.f, s1 = 0.f;
#pragma unroll
            for (int ni = 0; ni < 4; ni++) {
                int cl = (wn & 1) * 32 + ni * 8 + 2 * c;
                __half h00 = __float2half_rn(__expf(fmaf(bbv[mi][0], acc[mi][ni][0], cbv[mi][0])));
                __half h01 = __float2half_rn(__expf(fmaf(bbv[mi][0], acc[mi][ni][1], cbv[mi][0])));
                __half h10 = __float2half_rn(__expf(fmaf(bbv[mi][1], acc[mi][ni][2], cbv[mi][1])));
                __half h11 = __float2half_rn(__expf(fmaf(bbv[mi][1], acc[mi][ni][3], cbv[mi][1])));
                s0 += __half2float(h00) + __half2float(h01);
                s1 += __half2float(h10) + __half2float(h11);
                if (store_w) {
                    *(__half2*)&Sp[swzh(r0, cl)] = __halves2half2(h00, h01);
                    *(__half2*)&Sp[swzh(r0 + 8, cl)] = __halves2half2(h10, h11);
                }
            }
            s0 += __shfl_xor_sync(0xffffffffu, s0, 1);
            s0 += __shfl_xor_sync(0xffffffffu, s0, 2);
            s1 += __shfl_xor_sync(0xffffffffu, s1, 1);
            s1 += __shfl_xor_sync(0xffffffffu, s1, 2);
            if (c == 0) {
                lsum[r0 * 4 + wn] = s0;
                lsum[(r0 + 8) * 4 + wn] = s1;
            }
        }
        __syncthreads();
        if (tid < 128) {
            float tot = lsum[tid * 4 + 0] + lsum[tid * 4 + 1] +
                        lsum[tid * 4 + 2] + lsum[tid * 4 + 3];
            g_lpart[(size_t)(by * BM + tid) * (NP / BN) + tile] = tot;
        }
        __syncthreads();
    }
}

// =================================================================
// GEMM2: part[z] = W * P, grid (4, 8, 9) = 288 CTAs, same pipeline
// =================================================================
__global__ __launch_bounds__(256, 2) void gemm2_ms() {
    extern __shared__ float sm[];
    const uint32_t sbase = (uint32_t)__cvta_generic_to_shared(sm);

    const int tid = threadIdx.x;
    const int wid = tid >> 5, lane = tid & 31;
    const int wm = wid >> 2, wn = wid & 3;
    const int g = lane >> 2, c = lane & 3;
    const int bx = blockIdx.x, by = blockIdx.y, bz = blockIdx.z;
    const int s0 = (bz * 1024) / KSPLIT, s1 = ((bz + 1) * 1024) / KSPLIT;
    const int nit = s1 - s0;
    FRAG_CONSTS()

    if (tid == 0) {
#pragma unroll
        for (int b = 0; b < NSTG; b++) {
            mbar_init(sbase + 8 * b, 1);
            mbar_init(sbase + 24 + 8 * b, 8);
        }
        asm volatile("fence.proxy.async.shared::cta;" ::: "memory");
    }
    __syncthreads();

    auto stage = [&](int u) {
        int b = u % NSTG;
        uint32_t mbar = sbase + 8 * b;
        uint32_t da = sbase + RING_OFF + b * STAGE_B;
        mbar_expect_tx(mbar, STAGE_B);
        bulk_g2s(da, g_S_h + ((size_t)by * 1024 + s0 + u) * PANEL_H, PANEL_B, mbar);
        bulk_g2s(da + PANEL_B, g_pattT_h + ((size_t)bx * 1024 + s0 + u) * PANEL_H,
                 PANEL_B, mbar);
    };
    if (tid == 0) { stage(0); stage(1); stage(2); }

    float acc[4][4][4];
#pragma unroll
    for (int i = 0; i < 4; i++)
#pragma unroll
        for (int j = 0; j < 4; j++)
#pragma unroll
            for (int r = 0; r < 4; r++) acc[i][j][r] = 0.f;

    for (int s = 0; s < nit; s++) {
        PIPE_STAGE(s, nit, stage)
    }

    float* Dp = g_part + (size_t)bz * (BQ * DD) + (size_t)(by * BM) * DD + bx * BN;
#pragma unroll
    for (int mi = 0; mi < 4; mi++) {
        int r0 = wm * 64 + mi * 16 + g;
#pragma unroll
        for (int ni = 0; ni < 4; ni++) {
            int col = wn * 32 + ni * 8 + c * 2;
            float2 v0 = make_float2(acc[mi][ni][0], acc[mi][ni][1]);
            float2 v1 = make_float2(acc[mi][ni][2], acc[mi][ni][3]);
            *(float2*)&Dp[(size_t)r0 * DD + col] = v0;
            *(float2*)&Dp[(size_t)(r0 + 8) * DD + col] = v1;
        }
    }
}

// =================================================================
// Pattern prep (once): fp16 into tiled g_patt_h and g_pattT_h
// =================================================================
__global__ __launch_bounds__(256) void pat_prep_kernel(const float* __restrict__ pat) {
    __shared__ float t[64][65];
    int n0 = blockIdx.x * 64, d0 = blockIdx.y * 64;
    int tid = threadIdx.x;
#pragma unroll
    for (int j = 0; j < 16; j++) {
        int i = tid + j * 256;
        int nl = i >> 6, dl = i & 63;
        t[nl][dl] = pat[(size_t)(n0 + nl) * DD + d0 + dl];
    }
    __syncthreads();
#pragma unroll
    for (int j = 0; j < 8; j++) {
        int i = tid + j * 256;
        int nl = i >> 5, pc = i & 31;
        int n = n0 + nl;
        __half2 v = __floats2half2_rn(t[nl][2 * pc], t[nl][2 * pc + 1]);
        size_t panel = (size_t)(n >> 7) * 8 + (d0 >> 6);
        *(__half2*)&g_patt_h[panel * PANEL_H + swzh(n & 127, 2 * pc)] = v;
    }
#pragma unroll
    for (int j = 0; j < 8; j++) {
        int i = tid + j * 256;
        int dl = i >> 5, pc = i & 31;
        int d = d0 + dl;
        __half2 v = __floats2half2_rn(t[2 * pc][dl], t[2 * pc + 1][dl]);
        size_t panel = (size_t)(d >> 7) * 1024 + (n0 >> 6);
        *(__half2*)&g_pattT_h[panel * PANEL_H + swzh(d & 127, 2 * pc)] = v;
    }
}

// =================================================================
// Combine (fused lsum+energy): l = sum lpart row; energy(step);
// state = (sum partials)/l; write fp16(state/b) tiled; new ssq/b/coefs
// =================================================================
__global__ __launch_bounds__(512) void combine_kernel(int step) {
    const int row = blockIdx.x;
    const int d = threadIdx.x;
    const int lane = d & 31, wrp = d >> 5;
    __shared__ float red[16];
    __shared__ float sh_l, sh_invb;

    float ls = g_lpart[(size_t)row * (NP / BN) + d];
#pragma unroll
    for (int o = 16; o; o >>= 1) ls += __shfl_xor_sync(0xffffffffu, ls, o);
    if (lane == 0) red[wrp] = ls;
    __syncthreads();
    if (d == 0) {
        float l = 0.f;
#pragma unroll
        for (int i = 0; i < 16; i++) l += red[i];
        sh_l = l;
        g_energy[step * BQ + row] = g_eb[row] - logf(l) + 0.5f * g_ssq[row];
    }
    __syncthreads();

    float s = 0.f;
#pragma unroll
    for (int z = 0; z < KSPLIT; z++)
        s += g_part[(size_t)z * (BQ * DD) + (size_t)row * DD + d];
    float v = s / sh_l;
    g_state[(size_t)row * DD + d] = v;
    float ss = v * v;
#pragma unroll
    for (int o = 16; o; o >>= 1) ss += __shfl_xor_sync(0xffffffffu, ss, o);
    if (lane == 0) red[wrp] = ss;
    __syncthreads();
    if (d == 0) {
        float tot = 0.f;
#pragma unroll
        for (int i = 0; i < 16; i++) tot += red[i];
        float b = sqrtf(tot);
        float k = floorf(b * 1.44269504f);
        g_ssq[row] = tot;
        g_ea[row] = b;
        g_eb[row] = k * 0.69314718056f - b;
        sh_invb = 1.0f / b;
    }
    __syncthreads();
    __half hv = __float2half_rn(v * sh_invb);
    g_state_ht[((size_t)(row >> 7) * 8 + (d >> 6)) * PANEL_H + swzh(row & 127, d & 63)] = hv;
}

// final-step energy only
__global__ __launch_bounds__(512) void lsum_energy_kernel(int step) {
    const int row = blockIdx.x;
    const int d = threadIdx.x;
    const int lane = d & 31, wrp = d >> 5;
    __shared__ float red[16];
    float ls = g_lpart[(size_t)row * (NP / BN) + d];
#pragma unroll
    for (int o = 16; o; o >>= 1) ls += __shfl_xor_sync(0xffffffffu, ls, o);
    if (lane == 0) red[wrp] = ls;
    __syncthreads();
    if (d == 0) {
        float l = 0.f;
#pragma unroll
        for (int i = 0; i < 16; i++) l += red[i];
        g_energy[step * BQ + row] = g_eb[row] - logf(l) + 0.5f * g_ssq[row];
    }
}

__global__ __launch_bounds__(512) void init_state_kernel(const float* __restrict__ q) {
    const int row = blockIdx.x;
    const int d = threadIdx.x;
    const int lane = d & 31, wrp = d >> 5;
    __shared__ float red[16];
    __shared__ float sh_invb;
    float v = q[(size_t)row * DD + d];
    g_state[(size_t)row * DD + d] = v;
    float ss = v * v;
#pragma unroll
    for (int o = 16; o; o >>= 1) ss += __shfl_xor_sync(0xffffffffu, ss, o);
    if (lane == 0) red[wrp] = ss;
    __syncthreads();
    if (d == 0) {
        float tot = 0.f;
#pragma unroll
        for (int i = 0; i < 16; i++) tot += red[i];
        float b = sqrtf(tot);
        float k = floorf(b * 1.44269504f);
        g_ssq[row] = tot;
        g_ea[row] = b;
        g_eb[row] = k * 0.69314718056f - b;
        sh_invb = 1.0f / b;
    }
    __syncthreads();
    __half hv = __float2half_rn(v * sh_invb);
    g_state_ht[((size_t)(row >> 7) * 8 + (d >> 6)) * PANEL_H + swzh(row & 127, d & 63)] = hv;
}

__global__ __launch_bounds__(256) void pack_kernel(float* __restrict__ out, int total) {
    int i = blockIdx.x * 256 + threadIdx.x;
    if (i >= total) return;
    if (i < BQ * DD) {
        out[i] = g_state[i];
    } else {
        int e = i - BQ * DD;
        if (e < (NSTEPS + 1) * BQ) out[i] = g_energy[e];
    }
}

// =================================================================
// launch
// =================================================================
extern "C" void kernel_launch(void* const* d_in, const int* in_sizes, int n_in,
                              void* d_out, int out_size) {
    const float* query = (const float*)d_in[0];
    const float* patterns = (const float*)d_in[1];
    if (n_in >= 2 && in_sizes[0] != BQ * DD) {
        const float* t = query;
        query = patterns;
        patterns = t;
    }
    float* out = (float*)d_out;

    cudaFuncSetAttribute(gemm1_ms, cudaFuncAttributeMaxDynamicSharedMemorySize, SMEM_BYTES);
    cudaFuncSetAttribute(gemm2_ms, cudaFuncAttributeMaxDynamicSharedMemorySize, SMEM_BYTES);

    init_state_kernel<<<BQ, 512>>>(query);
    pat_prep_kernel<<<dim3(NP / 64, DD / 64), 256>>>(patterns);

    dim3 g1grid(NT1, BQ / BM, 1);            // (37, 8) = 296 CTAs, single wave
    dim3 g2grid(DD / BN, BQ / BM, KSPLIT);   // (4, 8, 9) = 288 CTAs, single wave

    for (int t = 0; t < NSTEPS; t++) {
        gemm1_ms<<<g1grid, 256, SMEM_BYTES>>>(1);
        gemm2_ms<<<g2grid, 256, SMEM_BYTES>>>();
        combine_kernel<<<BQ, 512>>>(t);
    }
    gemm1_ms<<<g1grid, 256, SMEM_BYTES>>>(0);
    lsum_energy_kernel<<<BQ, 512>>>(NSTEPS);

    pack_kernel<<<(out_size + 255) / 256, 256>>>(out, out_size);
}

// round 14
// speedup vs baseline: 1.4285x; 1.4285x over previous
#include <cuda_runtime.h>
#include <cuda_fp16.h>
#include <stdint.h>

#define BQ 1024
#define DD 512
#define NP 65536
#define NSTEPS 10
#define KSPLIT 9
#define NT1 37                              // GEMM1 grid.x (persistent): 37*8=296 CTAs

#define BM 128
#define BN 128
#define BK 64
#define PANEL_H 8192                        // halves per 128x64 fp16 panel
#define PANEL_B 16384                       // bytes per panel
#define STAGE_B (2 * PANEL_B)               // A + B per stage
#define NSTG 3
#define RING_OFF 5120                       // bytes: 1024 hdr (mbars) + 4096 lsum scratch
#define SMEM_BYTES (RING_OFF + NSTG * STAGE_B)   // 103424 -> 2 CTAs/SM

// mbar layout (bytes from sbase): full[b] at 8*b, empty[b] at 24 + 8*b

// ---------------- tiled global scratch (device globals; no allocation) ----------------
// fp16 panel [128 r][64 cl], SW128: half index = r*64 + (((cl>>1) ^ ((r&7)<<2))<<1) + (cl&1)
__device__ __half g_S_h[(size_t)8 * 1024 * PANEL_H];     // weights tiled [mblk][kstg] 134MB
__device__ __half g_patt_h[(size_t)512 * 8 * PANEL_H];   // P tiled [nblk][dstg]        67MB
__device__ __half g_pattT_h[(size_t)4 * 1024 * PANEL_H]; // P^T tiled [jblk][nstg]      67MB
__device__ __half g_state_ht[(size_t)8 * 8 * PANEL_H];   // fp16(state/b) tiled          1MB
__device__ float g_state[BQ * DD];                       // fp32 state (output)
__device__ float g_lpart[(size_t)BQ * (NP / BN)];        // per-tile weight sums
__device__ float g_ssq[BQ];
__device__ float g_ea[BQ];                               // b = ||state||
__device__ float g_eb[BQ];                               // k*ln2 - b  (k = floor(b/ln2))
__device__ float g_energy[(NSTEPS + 1) * BQ];
__device__ float g_part[(size_t)KSPLIT * BQ * DD];       // GEMM2 split-K partials 18MB

// ---------------- helpers ----------------
__device__ __forceinline__ uint32_t swzh(uint32_t r, uint32_t cl) {
    return r * 64u + ((((cl >> 1) ^ ((r & 7u) << 2)) << 1)) + (cl & 1u);
}
__device__ __forceinline__ void mbar_init(uint32_t addr, uint32_t cnt) {
    asm volatile("mbarrier.init.shared.b64 [%0], %1;" ::"r"(addr), "r"(cnt) : "memory");
}
__device__ __forceinline__ void mbar_expect_tx(uint32_t addr, uint32_t bytes) {
    asm volatile("mbarrier.arrive.expect_tx.shared.b64 _, [%0], %1;"
                 ::"r"(addr), "r"(bytes) : "memory");
}
__device__ __forceinline__ void mbar_arrive(uint32_t addr) {
    asm volatile("mbarrier.arrive.shared.b64 _, [%0];" ::"r"(addr) : "memory");
}
__device__ __forceinline__ void mbar_wait(uint32_t addr, uint32_t parity) {
    asm volatile(
        "{\n\t.reg .pred P1;\n\t"
        "WAIT_%=:\n\t"
        "mbarrier.try_wait.parity.acquire.cta.shared::cta.b64 P1, [%0], %1, 0x989680;\n\t"
        "@!P1 bra WAIT_%=;\n\t"
        "}"
        ::"r"(addr), "r"(parity) : "memory");
}
__device__ __forceinline__ void bulk_g2s(uint32_t daddr, const void* src, uint32_t bytes,
                                         uint32_t mbar) {
    asm volatile(
        "cp.async.bulk.shared::cluster.global.mbarrier::complete_tx::bytes "
        "[%0], [%1], %2, [%3];"
        ::"r"(daddr), "l"(src), "r"(bytes), "r"(mbar) : "memory");
}

// fragment load for one kk (scalar LDS — proven fast in R12)
#define FRAG_LOAD(kk, As32, Bs32)                                                      \
    {                                                                                  \
        const int x0 = (8 * (kk) + c) ^ (g << 2);                                      \
        const int x1 = (8 * (kk) + c + 4) ^ (g << 2);                                  \
        _Pragma("unroll") for (int mi = 0; mi < 4; mi++) {                             \
            int r0 = wm * 64 + mi * 16 + g;                                            \
            af[mi][0] = (As32)[r0 * 32 + x0];                                          \
            af[mi][1] = (As32)[(r0 + 8) * 32 + x0];                                    \
            af[mi][2] = (As32)[r0 * 32 + x1];                                          \
            af[mi][3] = (As32)[(r0 + 8) * 32 + x1];                                    \
        }                                                                              \
        _Pragma("unroll") for (int ni = 0; ni < 4; ni++) {                             \
            int nr = wn * 32 + ni * 8 + g;                                             \
            bf[ni][0] = (Bs32)[nr * 32 + x0];                                          \
            bf[ni][1] = (Bs32)[nr * 32 + x1];                                          \
        }                                                                              \
    }

#define FRAG_MMA()                                                                     \
    _Pragma("unroll") for (int mi = 0; mi < 4; mi++)                                   \
        _Pragma("unroll") for (int ni = 0; ni < 4; ni++) {                             \
            asm volatile(                                                              \
                "mma.sync.aligned.m16n8k16.row.col.f32.f16.f16.f32 "                   \
                "{%0,%1,%2,%3}, {%4,%5,%6,%7}, {%8,%9}, {%0,%1,%2,%3};\n"              \
                : "+f"(acc[mi][ni][0]), "+f"(acc[mi][ni][1]),                          \
                  "+f"(acc[mi][ni][2]), "+f"(acc[mi][ni][3])                           \
                : "r"(af[mi][0]), "r"(af[mi][1]), "r"(af[mi][2]), "r"(af[mi][3]),      \
                  "r"(bf[ni][0]), "r"(bf[ni][1]));                                     \
        }

// consume stage u: empty-arrive is placed AFTER the last fragment load
// (buffer is free once values are in registers) so the drain — and hence the
// producer's refill — completes ~one MMA-burst earlier than in R12.
#define PIPE_STAGE(u, total, STAGE_FN)                                                 \
    {                                                                                  \
        int b_ = (u) % NSTG;                                                           \
        uint32_t fullb_ = sbase + 8 * b_;                                              \
        uint32_t emptyb_ = sbase + 24 + 8 * b_;                                        \
        uint32_t par_ = ((u) / NSTG) & 1;                                              \
        mbar_wait(fullb_, par_);                                                       \
        const uint32_t* As32 =                                                         \
            (const uint32_t*)((const char*)sm + RING_OFF + b_ * STAGE_B);              \
        const uint32_t* Bs32 = As32 + PANEL_B / 4;                                     \
        uint32_t af[4][4], bf[4][2];                                                   \
        FRAG_LOAD(0, As32, Bs32) FRAG_MMA()                                            \
        FRAG_LOAD(1, As32, Bs32) FRAG_MMA()                                            \
        FRAG_LOAD(2, As32, Bs32) FRAG_MMA()                                            \
        FRAG_LOAD(3, As32, Bs32)                                                       \
        if (lane == 0) mbar_arrive(emptyb_);                                           \
        FRAG_MMA()                                                                     \
        if (tid == 0 && (u) + NSTG < (total)) {                                        \
            mbar_wait(emptyb_, par_);                                                  \
            STAGE_FN((u) + NSTG);                                                      \
        }                                                                              \
    }

// =================================================================
// GEMM1 (persistent): grid (37, 8), 256 threads, 2 CTAs/SM.
// producer/consumer mbarrier pipeline; epilogue w'=exp(b*acc+cb) + row sums
// =================================================================
__global__ __launch_bounds__(256, 2) void gemm1_ms(int store_w) {
    extern __shared__ float sm[];
    const uint32_t sbase = (uint32_t)__cvta_generic_to_shared(sm);

    const int tid = threadIdx.x;
    const int wid = tid >> 5, lane = tid & 31;
    const int wm = wid >> 2, wn = wid & 3;
    const int g = lane >> 2, c = lane & 3;
    const int bx = blockIdx.x, by = blockIdx.y;
    const int t0 = (bx * 512) / NT1, t1 = ((bx + 1) * 512) / NT1;
    const int total = (t1 - t0) * 8;

    if (tid == 0) {
#pragma unroll
        for (int b = 0; b < NSTG; b++) {
            mbar_init(sbase + 8 * b, 1);       // full
            mbar_init(sbase + 24 + 8 * b, 8);  // empty (8 warps)
        }
        asm volatile("fence.proxy.async.shared::cta;" ::: "memory");
    }
    __syncthreads();

    auto stage = [&](int u) {
        int b = u % NSTG;
        uint32_t mbar = sbase + 8 * b;
        uint32_t da = sbase + RING_OFF + b * STAGE_B;
        int tile = t0 + (u >> 3), k = u & 7;
        mbar_expect_tx(mbar, STAGE_B);
        bulk_g2s(da, g_state_ht + ((size_t)by * 8 + k) * PANEL_H, PANEL_B, mbar);
        bulk_g2s(da + PANEL_B, g_patt_h + ((size_t)tile * 8 + k) * PANEL_H, PANEL_B, mbar);
    };
    if (tid == 0) { stage(0); stage(1); stage(2); }

    float bbv[4][2], cbv[4][2];
#pragma unroll
    for (int mi = 0; mi < 4; mi++) {
        int r0 = wm * 64 + mi * 16 + g;
        bbv[mi][0] = g_ea[by * BM + r0];
        cbv[mi][0] = g_eb[by * BM + r0];
        bbv[mi][1] = g_ea[by * BM + r0 + 8];
        cbv[mi][1] = g_eb[by * BM + r0 + 8];
    }

    float* lsum = sm + 256;  // bytes [1024, 5120): dedicated scratch, [128][4]

    int u = 0;
    for (int tile = t0; tile < t1; tile++) {
        float acc[4][4][4];
#pragma unroll
        for (int i = 0; i < 4; i++)
#pragma unroll
            for (int j = 0; j < 4; j++)
#pragma unroll
                for (int r = 0; r < 4; r++) acc[i][j][r] = 0.f;

        for (int k = 0; k < 8; k++, u++) {
            PIPE_STAGE(u, total, stage)
        }

        // ---- epilogue: w' = exp(b*acc + cb), fp16 tiled store + row sums ----
        __half* Sp = g_S_h + ((size_t)by * 1024 + tile * 2 + (wn >> 1)) * PANEL_H;
#pragma unroll
        for (int mi = 0; mi < 4; mi++) {
            int r0 = wm * 64 + mi * 16 + g;
            float s0 = 0.f, s1 = 0.f;
#pragma unroll
            for (int ni = 0; ni < 4; ni++) {
                int cl = (wn & 1) * 32 + ni * 8 + 2 * c;
                __half h00 = __float2half_rn(__expf(fmaf(bbv[mi][0], acc[mi][ni][0], cbv[mi][0])));
                __half h01 = __float2half_rn(__expf(fmaf(bbv[mi][0], acc[mi][ni][1], cbv[mi][0])));
                __half h10 = __float2half_rn(__expf(fmaf(bbv[mi][1], acc[mi][ni][2], cbv[mi][1])));
                __half h11 = __float2half_rn(__expf(fmaf(bbv[mi][1], acc[mi][ni][3], cbv[mi][1])));
                s0 += __half2float(h00) + __half2float(h01);
                s1 += __half2float(h10) + __half2float(h11);
                if (store_w) {
                    *(__half2*)&Sp[swzh(r0, cl)] = __halves2half2(h00, h01);
                    *(__half2*)&Sp[swzh(r0 + 8, cl)] = __halves2half2(h10, h11);
                }
            }
            s0 += __shfl_xor_sync(0xffffffffu, s0, 1);
            s0 += __shfl_xor_sync(0xffffffffu, s0, 2);
            s1 += __shfl_xor_sync(0xffffffffu, s1, 1);
            s1 += __shfl_xor_sync(0xffffffffu, s1, 2);
            if (c == 0) {
                lsum[r0 * 4 + wn] = s0;
                lsum[(r0 + 8) * 4 + wn] = s1;
            }
        }
        __syncthreads();
        if (tid < 128) {
            float tot = lsum[tid * 4 + 0] + lsum[tid * 4 + 1] +
                        lsum[tid * 4 + 2] + lsum[tid * 4 + 3];
            g_lpart[(size_t)(by * BM + tid) * (NP / BN) + tile] = tot;
        }
        __syncthreads();
    }
}

// =================================================================
// GEMM2: part[z] = W * P, grid (4, 8, 9) = 288 CTAs, same pipeline
// =================================================================
__global__ __launch_bounds__(256, 2) void gemm2_ms() {
    extern __shared__ float sm[];
    const uint32_t sbase = (uint32_t)__cvta_generic_to_shared(sm);

    const int tid = threadIdx.x;
    const int wid = tid >> 5, lane = tid & 31;
    const int wm = wid >> 2, wn = wid & 3;
    const int g = lane >> 2, c = lane & 3;
    const int bx = blockIdx.x, by = blockIdx.y, bz = blockIdx.z;
    const int s0 = (bz * 1024) / KSPLIT, s1 = ((bz + 1) * 1024) / KSPLIT;
    const int nit = s1 - s0;

    if (tid == 0) {
#pragma unroll
        for (int b = 0; b < NSTG; b++) {
            mbar_init(sbase + 8 * b, 1);
            mbar_init(sbase + 24 + 8 * b, 8);
        }
        asm volatile("fence.proxy.async.shared::cta;" ::: "memory");
    }
    __syncthreads();

    auto stage = [&](int u) {
        int b = u % NSTG;
        uint32_t mbar = sbase + 8 * b;
        uint32_t da = sbase + RING_OFF + b * STAGE_B;
        mbar_expect_tx(mbar, STAGE_B);
        bulk_g2s(da, g_S_h + ((size_t)by * 1024 + s0 + u) * PANEL_H, PANEL_B, mbar);
        bulk_g2s(da + PANEL_B, g_pattT_h + ((size_t)bx * 1024 + s0 + u) * PANEL_H,
                 PANEL_B, mbar);
    };
    if (tid == 0) { stage(0); stage(1); stage(2); }

    float acc[4][4][4];
#pragma unroll
    for (int i = 0; i < 4; i++)
#pragma unroll
        for (int j = 0; j < 4; j++)
#pragma unroll
            for (int r = 0; r < 4; r++) acc[i][j][r] = 0.f;

    for (int s = 0; s < nit; s++) {
        PIPE_STAGE(s, nit, stage)
    }

    float* Dp = g_part + (size_t)bz * (BQ * DD) + (size_t)(by * BM) * DD + bx * BN;
#pragma unroll
    for (int mi = 0; mi < 4; mi++) {
        int r0 = wm * 64 + mi * 16 + g;
#pragma unroll
        for (int ni = 0; ni < 4; ni++) {
            int col = wn * 32 + ni * 8 + c * 2;
            float2 v0 = make_float2(acc[mi][ni][0], acc[mi][ni][1]);
            float2 v1 = make_float2(acc[mi][ni][2], acc[mi][ni][3]);
            *(float2*)&Dp[(size_t)r0 * DD + col] = v0;
            *(float2*)&Dp[(size_t)(r0 + 8) * DD + col] = v1;
        }
    }
}

// =================================================================
// Pattern prep (once): fp16 into tiled g_patt_h and g_pattT_h
// =================================================================
__global__ __launch_bounds__(256) void pat_prep_kernel(const float* __restrict__ pat) {
    __shared__ float t[64][65];
    int n0 = blockIdx.x * 64, d0 = blockIdx.y * 64;
    int tid = threadIdx.x;
#pragma unroll
    for (int j = 0; j < 16; j++) {
        int i = tid + j * 256;
        int nl = i >> 6, dl = i & 63;
        t[nl][dl] = pat[(size_t)(n0 + nl) * DD + d0 + dl];
    }
    __syncthreads();
#pragma unroll
    for (int j = 0; j < 8; j++) {
        int i = tid + j * 256;
        int nl = i >> 5, pc = i & 31;
        int n = n0 + nl;
        __half2 v = __floats2half2_rn(t[nl][2 * pc], t[nl][2 * pc + 1]);
        size_t panel = (size_t)(n >> 7) * 8 + (d0 >> 6);
        *(__half2*)&g_patt_h[panel * PANEL_H + swzh(n & 127, 2 * pc)] = v;
    }
#pragma unroll
    for (int j = 0; j < 8; j++) {
        int i = tid + j * 256;
        int dl = i >> 5, pc = i & 31;
        int d = d0 + dl;
        __half2 v = __floats2half2_rn(t[2 * pc][dl], t[2 * pc + 1][dl]);
        size_t panel = (size_t)(d >> 7) * 1024 + (n0 >> 6);
        *(__half2*)&g_pattT_h[panel * PANEL_H + swzh(d & 127, 2 * pc)] = v;
    }
}

// =================================================================
// Combine (fused lsum+energy): l = sum lpart row; energy(step);
// state = (sum partials)/l; write fp16(state/b) tiled; new ssq/b/coefs
// =================================================================
__global__ __launch_bounds__(512) void combine_kernel(int step) {
    const int row = blockIdx.x;
    const int d = threadIdx.x;
    const int lane = d & 31, wrp = d >> 5;
    __shared__ float red[16];
    __shared__ float sh_l, sh_invb;

    float ls = g_lpart[(size_t)row * (NP / BN) + d];
#pragma unroll
    for (int o = 16; o; o >>= 1) ls += __shfl_xor_sync(0xffffffffu, ls, o);
    if (lane == 0) red[wrp] = ls;
    __syncthreads();
    if (d == 0) {
        float l = 0.f;
#pragma unroll
        for (int i = 0; i < 16; i++) l += red[i];
        sh_l = l;
        g_energy[step * BQ + row] = g_eb[row] - logf(l) + 0.5f * g_ssq[row];
    }
    __syncthreads();

    float s = 0.f;
#pragma unroll
    for (int z = 0; z < KSPLIT; z++)
        s += g_part[(size_t)z * (BQ * DD) + (size_t)row * DD + d];
    float v = s / sh_l;
    g_state[(size_t)row * DD + d] = v;
    float ss = v * v;
#pragma unroll
    for (int o = 16; o; o >>= 1) ss += __shfl_xor_sync(0xffffffffu, ss, o);
    if (lane == 0) red[wrp] = ss;
    __syncthreads();
    if (d == 0) {
        float tot = 0.f;
#pragma unroll
        for (int i = 0; i < 16; i++) tot += red[i];
        float b = sqrtf(tot);
        float k = floorf(b * 1.44269504f);
        g_ssq[row] = tot;
        g_ea[row] = b;
        g_eb[row] = k * 0.69314718056f - b;
        sh_invb = 1.0f / b;
    }
    __syncthreads();
    __half hv = __float2half_rn(v * sh_invb);
    g_state_ht[((size_t)(row >> 7) * 8 + (d >> 6)) * PANEL_H + swzh(row & 127, d & 63)] = hv;
}

// final-step energy only
__global__ __launch_bounds__(512) void lsum_energy_kernel(int step) {
    const int row = blockIdx.x;
    const int d = threadIdx.x;
    const int lane = d & 31, wrp = d >> 5;
    __shared__ float red[16];
    float ls = g_lpart[(size_t)row * (NP / BN) + d];
#pragma unroll
    for (int o = 16; o; o >>= 1) ls += __shfl_xor_sync(0xffffffffu, ls, o);
    if (lane == 0) red[wrp] = ls;
    __syncthreads();
    if (d == 0) {
        float l = 0.f;
#pragma unroll
        for (int i = 0; i < 16; i++) l += red[i];
        g_energy[step * BQ + row] = g_eb[row] - logf(l) + 0.5f * g_ssq[row];
    }
}

__global__ __launch_bounds__(512) void init_state_kernel(const float* __restrict__ q) {
    const int row = blockIdx.x;
    const int d = threadIdx.x;
    const int lane = d & 31, wrp = d >> 5;
    __shared__ float red[16];
    __shared__ float sh_invb;
    float v = q[(size_t)row * DD + d];
    g_state[(size_t)row * DD + d] = v;
    float ss = v * v;
#pragma unroll
    for (int o = 16; o; o >>= 1) ss += __shfl_xor_sync(0xffffffffu, ss, o);
    if (lane == 0) red[wrp] = ss;
    __syncthreads();
    if (d == 0) {
        float tot = 0.f;
#pragma unroll
        for (int i = 0; i < 16; i++) tot += red[i];
        float b = sqrtf(tot);
        float k = floorf(b * 1.44269504f);
        g_ssq[row] = tot;
        g_ea[row] = b;
        g_eb[row] = k * 0.69314718056f - b;
        sh_invb = 1.0f / b;
    }
    __syncthreads();
    __half hv = __float2half_rn(v * sh_invb);
    g_state_ht[((size_t)(row >> 7) * 8 + (d >> 6)) * PANEL_H + swzh(row & 127, d & 63)] = hv;
}

__global__ __launch_bounds__(256) void pack_kernel(float* __restrict__ out, int total) {
    int i = blockIdx.x * 256 + threadIdx.x;
    if (i >= total) return;
    if (i < BQ * DD) {
        out[i] = g_state[i];
    } else {
        int e = i - BQ * DD;
        if (e < (NSTEPS + 1) * BQ) out[i] = g_energy[e];
    }
}

// =================================================================
// launch
// =================================================================
extern "C" void kernel_launch(void* const* d_in, const int* in_sizes, int n_in,
                              void* d_out, int out_size) {
    const float* query = (const float*)d_in[0];
    const float* patterns = (const float*)d_in[1];
    if (n_in >= 2 && in_sizes[0] != BQ * DD) {
        const float* t = query;
        query = patterns;
        patterns = t;
    }
    float* out = (float*)d_out;

    cudaFuncSetAttribute(gemm1_ms, cudaFuncAttributeMaxDynamicSharedMemorySize, SMEM_BYTES);
    cudaFuncSetAttribute(gemm2_ms, cudaFuncAttributeMaxDynamicSharedMemorySize, SMEM_BYTES);

    init_state_kernel<<<BQ, 512>>>(query);
    pat_prep_kernel<<<dim3(NP / 64, DD / 64), 256>>>(patterns);

    dim3 g1grid(NT1, BQ / BM, 1);            // (37, 8) = 296 CTAs, single wave
    dim3 g2grid(DD / BN, BQ / BM, KSPLIT);   // (4, 8, 9) = 288 CTAs, single wave

    for (int t = 0; t < NSTEPS; t++) {
        gemm1_ms<<<g1grid, 256, SMEM_BYTES>>>(1);
        gemm2_ms<<<g2grid, 256, SMEM_BYTES>>>();
        combine_kernel<<<BQ, 512>>>(t);
    }
    gemm1_ms<<<g1grid, 256, SMEM_BYTES>>>(0);
    lsum_energy_kernel<<<BQ, 512>>>(NSTEPS);

    pack_kernel<<<(out_size + 255) / 256, 256>>>(out, out_size);
}

// round 15
// speedup vs baseline: 1.5028x; 1.0520x over previous
#include <cuda_runtime.h>
#include <cuda_fp16.h>
#include <stdint.h>

#define BQ 1024
#define DD 512
#define NP 65536
#define NSTEPS 10
#define KSPLIT 9
#define NT1 37                              // GEMM1 grid.x (persistent): 37*8=296 CTAs

#define BM 128
#define BN 128
#define BK 64
#define PANEL_H 8192                        // halves per 128x64 fp16 panel
#define PANEL_B 16384                       // bytes per panel
#define STAGE_B (2 * PANEL_B)               // A + B per stage
#define NSTG 3
#define RING_OFF 5120                       // bytes: 1024 hdr (mbars) + 4096 lsum scratch
#define SMEM_BYTES (RING_OFF + NSTG * STAGE_B)   // 103424 -> 2 CTAs/SM
#define NTHR 128                            // 4 warps, warp grid 2(M) x 2(N), tile 64x64

// mbar layout (bytes from sbase): full[b] at 8*b, empty[b] at 24 + 8*b

// ---------------- tiled global scratch (device globals; no allocation) ----------------
// fp16 panel [128 r][64 cl], SW128: half index = r*64 + (((cl>>1) ^ ((r&7)<<2))<<1) + (cl&1)
__device__ __half g_S_h[(size_t)8 * 1024 * PANEL_H];     // weights tiled [mblk][kstg] 134MB
__device__ __half g_patt_h[(size_t)512 * 8 * PANEL_H];   // P tiled [nblk][dstg]        67MB
__device__ __half g_pattT_h[(size_t)4 * 1024 * PANEL_H]; // P^T tiled [jblk][nstg]      67MB
__device__ __half g_state_ht[(size_t)8 * 8 * PANEL_H];   // fp16(state/b) tiled          1MB
__device__ float g_state[BQ * DD];                       // fp32 state (output)
__device__ float g_lpart[(size_t)BQ * (NP / BN)];        // per-tile weight sums
__device__ float g_ssq[BQ];
__device__ float g_ea[BQ];                               // b = ||state||
__device__ float g_eb[BQ];                               // k*ln2 - b  (k = floor(b/ln2))
__device__ float g_energy[(NSTEPS + 1) * BQ];
__device__ float g_part[(size_t)KSPLIT * BQ * DD];       // GEMM2 split-K partials 18MB

// ---------------- helpers ----------------
__device__ __forceinline__ uint32_t swzh(uint32_t r, uint32_t cl) {
    return r * 64u + ((((cl >> 1) ^ ((r & 7u) << 2)) << 1)) + (cl & 1u);
}
__device__ __forceinline__ void mbar_init(uint32_t addr, uint32_t cnt) {
    asm volatile("mbarrier.init.shared.b64 [%0], %1;" ::"r"(addr), "r"(cnt) : "memory");
}
__device__ __forceinline__ void mbar_expect_tx(uint32_t addr, uint32_t bytes) {
    asm volatile("mbarrier.arrive.expect_tx.shared.b64 _, [%0], %1;"
                 ::"r"(addr), "r"(bytes) : "memory");
}
__device__ __forceinline__ void mbar_arrive(uint32_t addr) {
    asm volatile("mbarrier.arrive.shared.b64 _, [%0];" ::"r"(addr) : "memory");
}
__device__ __forceinline__ void mbar_wait(uint32_t addr, uint32_t parity) {
    asm volatile(
        "{\n\t.reg .pred P1;\n\t"
        "WAIT_%=:\n\t"
        "mbarrier.try_wait.parity.acquire.cta.shared::cta.b64 P1, [%0], %1, 0x989680;\n\t"
        "@!P1 bra WAIT_%=;\n\t"
        "}"
        ::"r"(addr), "r"(parity) : "memory");
}
__device__ __forceinline__ void bulk_g2s(uint32_t daddr, const void* src, uint32_t bytes,
                                         uint32_t mbar) {
    asm volatile(
        "cp.async.bulk.shared::cluster.global.mbarrier::complete_tx::bytes "
        "[%0], [%1], %2, [%3];"
        ::"r"(daddr), "l"(src), "r"(bytes), "r"(mbar) : "memory");
}

// fragment load for one kk (scalar LDS; warp tile 64x64: A 4x16-row, B 8x8-row)
#define FRAG_LOAD(kk, As32, Bs32)                                                      \
    {                                                                                  \
        const int x0 = (8 * (kk) + c) ^ (g << 2);                                      \
        const int x1 = (8 * (kk) + c + 4) ^ (g << 2);                                  \
        _Pragma("unroll") for (int mi = 0; mi < 4; mi++) {                             \
            int r0 = wm * 64 + mi * 16 + g;                                            \
            af[mi][0] = (As32)[r0 * 32 + x0];                                          \
            af[mi][1] = (As32)[(r0 + 8) * 32 + x0];                                    \
            af[mi][2] = (As32)[r0 * 32 + x1];                                          \
            af[mi][3] = (As32)[(r0 + 8) * 32 + x1];                                    \
        }                                                                              \
        _Pragma("unroll") for (int ni = 0; ni < 8; ni++) {                             \
            int nr = wn * 64 + ni * 8 + g;                                             \
            bf[ni][0] = (Bs32)[nr * 32 + x0];                                          \
            bf[ni][1] = (Bs32)[nr * 32 + x1];                                          \
        }                                                                              \
    }

#define FRAG_MMA()                                                                     \
    _Pragma("unroll") for (int mi = 0; mi < 4; mi++)                                   \
        _Pragma("unroll") for (int ni = 0; ni < 8; ni++) {                             \
            asm volatile(                                                              \
                "mma.sync.aligned.m16n8k16.row.col.f32.f16.f16.f32 "                   \
                "{%0,%1,%2,%3}, {%4,%5,%6,%7}, {%8,%9}, {%0,%1,%2,%3};\n"              \
                : "+f"(acc[mi][ni][0]), "+f"(acc[mi][ni][1]),                          \
                  "+f"(acc[mi][ni][2]), "+f"(acc[mi][ni][3])                           \
                : "r"(af[mi][0]), "r"(af[mi][1]), "r"(af[mi][2]), "r"(af[mi][3]),      \
                  "r"(bf[ni][0]), "r"(bf[ni][1]));                                     \
        }

// consume stage u; empty-arrive after last fragment load
#define PIPE_STAGE(u, total, STAGE_FN)                                                 \
    {                                                                                  \
        int b_ = (u) % NSTG;                                                           \
        uint32_t fullb_ = sbase + 8 * b_;                                              \
        uint32_t emptyb_ = sbase + 24 + 8 * b_;                                        \
        uint32_t par_ = ((u) / NSTG) & 1;                                              \
        mbar_wait(fullb_, par_);                                                       \
        const uint32_t* As32 =                                                         \
            (const uint32_t*)((const char*)sm + RING_OFF + b_ * STAGE_B);              \
        const uint32_t* Bs32 = As32 + PANEL_B / 4;                                     \
        uint32_t af[4][4], bf[8][2];                                                   \
        FRAG_LOAD(0, As32, Bs32) FRAG_MMA()                                            \
        FRAG_LOAD(1, As32, Bs32) FRAG_MMA()                                            \
        FRAG_LOAD(2, As32, Bs32) FRAG_MMA()                                            \
        FRAG_LOAD(3, As32, Bs32)                                                       \
        if (lane == 0) mbar_arrive(emptyb_);                                           \
        FRAG_MMA()                                                                     \
        if (tid == 0 && (u) + NSTG < (total)) {                                        \
            mbar_wait(emptyb_, par_);                                                  \
            STAGE_FN((u) + NSTG);                                                      \
        }                                                                              \
    }

// =================================================================
// GEMM1 (persistent): grid (37, 8), 128 threads, 2 CTAs/SM.
// =================================================================
__global__ __launch_bounds__(NTHR, 2) void gemm1_ms(int store_w) {
    extern __shared__ float sm[];
    const uint32_t sbase = (uint32_t)__cvta_generic_to_shared(sm);

    const int tid = threadIdx.x;
    const int wid = tid >> 5, lane = tid & 31;
    const int wm = wid >> 1, wn = wid & 1;
    const int g = lane >> 2, c = lane & 3;
    const int bx = blockIdx.x, by = blockIdx.y;
    const int t0 = (bx * 512) / NT1, t1 = ((bx + 1) * 512) / NT1;
    const int total = (t1 - t0) * 8;

    if (tid == 0) {
#pragma unroll
        for (int b = 0; b < NSTG; b++) {
            mbar_init(sbase + 8 * b, 1);       // full
            mbar_init(sbase + 24 + 8 * b, 4);  // empty (4 warps)
        }
        asm volatile("fence.proxy.async.shared::cta;" ::: "memory");
    }
    __syncthreads();

    auto stage = [&](int u) {
        int b = u % NSTG;
        uint32_t mbar = sbase + 8 * b;
        uint32_t da = sbase + RING_OFF + b * STAGE_B;
        int tile = t0 + (u >> 3), k = u & 7;
        mbar_expect_tx(mbar, STAGE_B);
        bulk_g2s(da, g_state_ht + ((size_t)by * 8 + k) * PANEL_H, PANEL_B, mbar);
        bulk_g2s(da + PANEL_B, g_patt_h + ((size_t)tile * 8 + k) * PANEL_H, PANEL_B, mbar);
    };
    if (tid == 0) { stage(0); stage(1); stage(2); }

    float bbv[4][2], cbv[4][2];
#pragma unroll
    for (int mi = 0; mi < 4; mi++) {
        int r0 = wm * 64 + mi * 16 + g;
        bbv[mi][0] = g_ea[by * BM + r0];
        cbv[mi][0] = g_eb[by * BM + r0];
        bbv[mi][1] = g_ea[by * BM + r0 + 8];
        cbv[mi][1] = g_eb[by * BM + r0 + 8];
    }

    float* lsum = sm + 256;  // bytes [1024, 5120): scratch, [128][2]

    int u = 0;
    for (int tile = t0; tile < t1; tile++) {
        float acc[4][8][4];
#pragma unroll
        for (int i = 0; i < 4; i++)
#pragma unroll
            for (int j = 0; j < 8; j++)
#pragma unroll
                for (int r = 0; r < 4; r++) acc[i][j][r] = 0.f;

        for (int k = 0; k < 8; k++, u++) {
            PIPE_STAGE(u, total, stage)
        }

        // ---- epilogue: w' = exp(b*acc + cb); wn selects the 64-col panel ----
        __half* Sp = g_S_h + ((size_t)by * 1024 + tile * 2 + wn) * PANEL_H;
#pragma unroll
        for (int mi = 0; mi < 4; mi++) {
            int r0 = wm * 64 + mi * 16 + g;
            float s0 = 0.f, s1 = 0.f;
#pragma unroll
            for (int ni = 0; ni < 8; ni++) {
                int cl = ni * 8 + 2 * c;
                __half h00 = __float2half_rn(__expf(fmaf(bbv[mi][0], acc[mi][ni][0], cbv[mi][0])));
                __half h01 = __float2half_rn(__expf(fmaf(bbv[mi][0], acc[mi][ni][1], cbv[mi][0])));
                __half h10 = __float2half_rn(__expf(fmaf(bbv[mi][1], acc[mi][ni][2], cbv[mi][1])));
                __half h11 = __float2half_rn(__expf(fmaf(bbv[mi][1], acc[mi][ni][3], cbv[mi][1])));
                s0 += __half2float(h00) + __half2float(h01);
                s1 += __half2float(h10) + __half2float(h11);
                if (store_w) {
                    *(__half2*)&Sp[swzh(r0, cl)] = __halves2half2(h00, h01);
                    *(__half2*)&Sp[swzh(r0 + 8, cl)] = __halves2half2(h10, h11);
                }
            }
            s0 += __shfl_xor_sync(0xffffffffu, s0, 1);
            s0 += __shfl_xor_sync(0xffffffffu, s0, 2);
            s1 += __shfl_xor_sync(0xffffffffu, s1, 1);
            s1 += __shfl_xor_sync(0xffffffffu, s1, 2);
            if (c == 0) {
                lsum[r0 * 2 + wn] = s0;
                lsum[(r0 + 8) * 2 + wn] = s1;
            }
        }
        __syncthreads();
        {
            float tot = lsum[tid * 2 + 0] + lsum[tid * 2 + 1];
            g_lpart[(size_t)(by * BM + tid) * (NP / BN) + tile] = tot;
        }
        __syncthreads();
    }
}

// =================================================================
// GEMM2: part[z] = W * P, grid (4, 8, 9) = 288 CTAs, same pipeline
// =================================================================
__global__ __launch_bounds__(NTHR, 2) void gemm2_ms() {
    extern __shared__ float sm[];
    const uint32_t sbase = (uint32_t)__cvta_generic_to_shared(sm);

    const int tid = threadIdx.x;
    const int wid = tid >> 5, lane = tid & 31;
    const int wm = wid >> 1, wn = wid & 1;
    const int g = lane >> 2, c = lane & 3;
    const int bx = blockIdx.x, by = blockIdx.y, bz = blockIdx.z;
    const int s0 = (bz * 1024) / KSPLIT, s1 = ((bz + 1) * 1024) / KSPLIT;
    const int nit = s1 - s0;

    if (tid == 0) {
#pragma unroll
        for (int b = 0; b < NSTG; b++) {
            mbar_init(sbase + 8 * b, 1);
            mbar_init(sbase + 24 + 8 * b, 4);
        }
        asm volatile("fence.proxy.async.shared::cta;" ::: "memory");
    }
    __syncthreads();

    auto stage = [&](int u) {
        int b = u % NSTG;
        uint32_t mbar = sbase + 8 * b;
        uint32_t da = sbase + RING_OFF + b * STAGE_B;
        mbar_expect_tx(mbar, STAGE_B);
        bulk_g2s(da, g_S_h + ((size_t)by * 1024 + s0 + u) * PANEL_H, PANEL_B, mbar);
        bulk_g2s(da + PANEL_B, g_pattT_h + ((size_t)bx * 1024 + s0 + u) * PANEL_H,
                 PANEL_B, mbar);
    };
    if (tid == 0) { stage(0); stage(1); stage(2); }

    float acc[4][8][4];
#pragma unroll
    for (int i = 0; i < 4; i++)
#pragma unroll
        for (int j = 0; j < 8; j++)
#pragma unroll
            for (int r = 0; r < 4; r++) acc[i][j][r] = 0.f;

    for (int s = 0; s < nit; s++) {
        PIPE_STAGE(s, nit, stage)
    }

    float* Dp = g_part + (size_t)bz * (BQ * DD) + (size_t)(by * BM) * DD + bx * BN;
#pragma unroll
    for (int mi = 0; mi < 4; mi++) {
        int r0 = wm * 64 + mi * 16 + g;
#pragma unroll
        for (int ni = 0; ni < 8; ni++) {
            int col = wn * 64 + ni * 8 + c * 2;
            float2 v0 = make_float2(acc[mi][ni][0], acc[mi][ni][1]);
            float2 v1 = make_float2(acc[mi][ni][2], acc[mi][ni][3]);
            *(float2*)&Dp[(size_t)r0 * DD + col] = v0;
            *(float2*)&Dp[(size_t)(r0 + 8) * DD + col] = v1;
        }
    }
}

// =================================================================
// Pattern prep (once): fp16 into tiled g_patt_h and g_pattT_h
// =================================================================
__global__ __launch_bounds__(256) void pat_prep_kernel(const float* __restrict__ pat) {
    __shared__ float t[64][65];
    int n0 = blockIdx.x * 64, d0 = blockIdx.y * 64;
    int tid = threadIdx.x;
#pragma unroll
    for (int j = 0; j < 16; j++) {
        int i = tid + j * 256;
        int nl = i >> 6, dl = i & 63;
        t[nl][dl] = pat[(size_t)(n0 + nl) * DD + d0 + dl];
    }
    __syncthreads();
#pragma unroll
    for (int j = 0; j < 8; j++) {
        int i = tid + j * 256;
        int nl = i >> 5, pc = i & 31;
        int n = n0 + nl;
        __half2 v = __floats2half2_rn(t[nl][2 * pc], t[nl][2 * pc + 1]);
        size_t panel = (size_t)(n >> 7) * 8 + (d0 >> 6);
        *(__half2*)&g_patt_h[panel * PANEL_H + swzh(n & 127, 2 * pc)] = v;
    }
#pragma unroll
    for (int j = 0; j < 8; j++) {
        int i = tid + j * 256;
        int dl = i >> 5, pc = i & 31;
        int d = d0 + dl;
        __half2 v = __floats2half2_rn(t[2 * pc][dl], t[2 * pc + 1][dl]);
        size_t panel = (size_t)(d >> 7) * 1024 + (n0 >> 6);
        *(__half2*)&g_pattT_h[panel * PANEL_H + swzh(d & 127, 2 * pc)] = v;
    }
}

// =================================================================
// Combine (fused lsum+energy)
// =================================================================
__global__ __launch_bounds__(512) void combine_kernel(int step) {
    const int row = blockIdx.x;
    const int d = threadIdx.x;
    const int lane = d & 31, wrp = d >> 5;
    __shared__ float red[16];
    __shared__ float sh_l, sh_invb;

    float ls = g_lpart[(size_t)row * (NP / BN) + d];
#pragma unroll
    for (int o = 16; o; o >>= 1) ls += __shfl_xor_sync(0xffffffffu, ls, o);
    if (lane == 0) red[wrp] = ls;
    __syncthreads();
    if (d == 0) {
        float l = 0.f;
#pragma unroll
        for (int i = 0; i < 16; i++) l += red[i];
        sh_l = l;
        g_energy[step * BQ + row] = g_eb[row] - logf(l) + 0.5f * g_ssq[row];
    }
    __syncthreads();

    float s = 0.f;
#pragma unroll
    for (int z = 0; z < KSPLIT; z++)
        s += g_part[(size_t)z * (BQ * DD) + (size_t)row * DD + d];
    float v = s / sh_l;
    g_state[(size_t)row * DD + d] = v;
    float ss = v * v;
#pragma unroll
    for (int o = 16; o; o >>= 1) ss += __shfl_xor_sync(0xffffffffu, ss, o);
    if (lane == 0) red[wrp] = ss;
    __syncthreads();
    if (d == 0) {
        float tot = 0.f;
#pragma unroll
        for (int i = 0; i < 16; i++) tot += red[i];
        float b = sqrtf(tot);
        float k = floorf(b * 1.44269504f);
        g_ssq[row] = tot;
        g_ea[row] = b;
        g_eb[row] = k * 0.69314718056f - b;
        sh_invb = 1.0f / b;
    }
    __syncthreads();
    __half hv = __float2half_rn(v * sh_invb);
    g_state_ht[((size_t)(row >> 7) * 8 + (d >> 6)) * PANEL_H + swzh(row & 127, d & 63)] = hv;
}

// final-step energy only
__global__ __launch_bounds__(512) void lsum_energy_kernel(int step) {
    const int row = blockIdx.x;
    const int d = threadIdx.x;
    const int lane = d & 31, wrp = d >> 5;
    __shared__ float red[16];
    float ls = g_lpart[(size_t)row * (NP / BN) + d];
#pragma unroll
    for (int o = 16; o; o >>= 1) ls += __shfl_xor_sync(0xffffffffu, ls, o);
    if (lane == 0) red[wrp] = ls;
    __syncthreads();
    if (d == 0) {
        float l = 0.f;
#pragma unroll
        for (int i = 0; i < 16; i++) l += red[i];
        g_energy[step * BQ + row] = g_eb[row] - logf(l) + 0.5f * g_ssq[row];
    }
}

__global__ __launch_bounds__(512) void init_state_kernel(const float* __restrict__ q) {
    const int row = blockIdx.x;
    const int d = threadIdx.x;
    const int lane = d & 31, wrp = d >> 5;
    __shared__ float red[16];
    __shared__ float sh_invb;
    float v = q[(size_t)row * DD + d];
    g_state[(size_t)row * DD + d] = v;
    float ss = v * v;
#pragma unroll
    for (int o = 16; o; o >>= 1) ss += __shfl_xor_sync(0xffffffffu, ss, o);
    if (lane == 0) red[wrp] = ss;
    __syncthreads();
    if (d == 0) {
        float tot = 0.f;
#pragma unroll
        for (int i = 0; i < 16; i++) tot += red[i];
        float b = sqrtf(tot);
        float k = floorf(b * 1.44269504f);
        g_ssq[row] = tot;
        g_ea[row] = b;
        g_eb[row] = k * 0.69314718056f - b;
        sh_invb = 1.0f / b;
    }
    __syncthreads();
    __half hv = __float2half_rn(v * sh_invb);
    g_state_ht[((size_t)(row >> 7) * 8 + (d >> 6)) * PANEL_H + swzh(row & 127, d & 63)] = hv;
}

__global__ __launch_bounds__(256) void pack_kernel(float* __restrict__ out, int total) {
    int i = blockIdx.x * 256 + threadIdx.x;
    if (i >= total) return;
    if (i < BQ * DD) {
        out[i] = g_state[i];
    } else {
        int e = i - BQ * DD;
        if (e < (NSTEPS + 1) * BQ) out[i] = g_energy[e];
    }
}

// =================================================================
// launch
// =================================================================
extern "C" void kernel_launch(void* const* d_in, const int* in_sizes, int n_in,
                              void* d_out, int out_size) {
    const float* query = (const float*)d_in[0];
    const float* patterns = (const float*)d_in[1];
    if (n_in >= 2 && in_sizes[0] != BQ * DD) {
        const float* t = query;
        query = patterns;
        patterns = t;
    }
    float* out = (float*)d_out;

    cudaFuncSetAttribute(gemm1_ms, cudaFuncAttributeMaxDynamicSharedMemorySize, SMEM_BYTES);
    cudaFuncSetAttribute(gemm2_ms, cudaFuncAttributeMaxDynamicSharedMemorySize, SMEM_BYTES);

    init_state_kernel<<<BQ, 512>>>(query);
    pat_prep_kernel<<<dim3(NP / 64, DD / 64), 256>>>(patterns);

    dim3 g1grid(NT1, BQ / BM, 1);            // (37, 8) = 296 CTAs, single wave
    dim3 g2grid(DD / BN, BQ / BM, KSPLIT);   // (4, 8, 9) = 288 CTAs, single wave

    for (int t = 0; t < NSTEPS; t++) {
        gemm1_ms<<<g1grid, NTHR, SMEM_BYTES>>>(1);
        gemm2_ms<<<g2grid, NTHR, SMEM_BYTES>>>();
        combine_kernel<<<BQ, 512>>>(t);
    }
    gemm1_ms<<<g1grid, NTHR, SMEM_BYTES>>>(0);
    lsum_energy_kernel<<<BQ, 512>>>(NSTEPS);

    pack_kernel<<<(out_size + 255) / 256, 256>>>(out, out_size);
}